// round 12
// baseline (speedup 1.0000x reference)
#include <cuda_runtime.h>
#include <cstdint>

// EmbedWeighted == out(B,D) = inputs(B,V) @ embeddings(V,D)
// Front-loaded demand: entire split tile (A 133KB + E 70KB) issued as cp.async
// at t=0; compute drains with progressive wait_group. tf32 mma.sync.
#define B_DIM 2048
#define V_DIM 2000
#define D_DIM 64
#define NSPLIT 8
#define KSPLIT 256            // splits 0..6: 256; split 7: 208 (mult of 16)
#define KC 32                 // k per drain stage (one cp.async group each)
#define NTHREADS 256
#define MTILE 128
#define NMTILE (B_DIM / MTILE)            // 16
#define A_STR 260             // words/row: 4 mod 32 -> frag banks distinct
#define E_STR 68              // words/row: 4 mod 32 -> frag banks distinct
#define DYN_BYTES ((MTILE * A_STR + KSPLIT * E_STR) * 4)   // 202752 B

__device__ float g_partials[NSPLIT][B_DIM][D_DIM];   // 4 MB static scratch
__device__ unsigned g_arrive[NMTILE];                // zero-init, self-resetting
__device__ unsigned g_done[NMTILE];

static __device__ __forceinline__ uint32_t f2tf32(float f) {
    uint32_t r; asm("cvt.rna.tf32.f32 %0, %1;" : "=r"(r) : "f"(f)); return r;
}
static __device__ __forceinline__ uint32_t smem_u32(const void* p) {
    return (uint32_t)__cvta_generic_to_shared(p);
}
static __device__ __forceinline__ uint32_t lds32(uint32_t a) {
    uint32_t v; asm("ld.shared.b32 %0, [%1];" : "=r"(v) : "r"(a)); return v;
}
static __device__ __forceinline__ float lds32f(uint32_t a) {
    float v; asm("ld.shared.f32 %0, [%1];" : "=f"(v) : "r"(a)); return v;
}
static __device__ __forceinline__ void cp_async16(uint32_t dst, const float* src, bool p) {
    int sz = p ? 16 : 0;   // src-size 0 => zero-fill 16B
    asm volatile("cp.async.cg.shared.global [%0], [%1], 16, %2;"
                 :: "r"(dst), "l"(src), "r"(sz));
}
static __device__ __forceinline__ void cp_commit() {
    asm volatile("cp.async.commit_group;");
}
static __device__ __forceinline__ void cp_wait_n(int n) {
    switch (n) {
        case 0: asm volatile("cp.async.wait_group 0;" ::: "memory"); break;
        case 1: asm volatile("cp.async.wait_group 1;" ::: "memory"); break;
        case 2: asm volatile("cp.async.wait_group 2;" ::: "memory"); break;
        case 3: asm volatile("cp.async.wait_group 3;" ::: "memory"); break;
        case 4: asm volatile("cp.async.wait_group 4;" ::: "memory"); break;
        case 5: asm volatile("cp.async.wait_group 5;" ::: "memory"); break;
        case 6: asm volatile("cp.async.wait_group 6;" ::: "memory"); break;
        default: asm volatile("cp.async.wait_group 7;" ::: "memory"); break;
    }
}

// 256 threads, 8 warps, warp tile 32x32 (2mt x 4nt). CTA tile M=128, N=64.
// grid (8, 16) = 128 CTAs, occ 1 (203KB smem) -> all co-resident.
__global__ __launch_bounds__(NTHREADS, 1)
void embedweighted_flood(const float* __restrict__ inp,
                         const float* __restrict__ emb,
                         float* __restrict__ out)
{
    extern __shared__ float smem[];
    const uint32_t abase = smem_u32(smem);                        // A[128][260] fp32
    const uint32_t ebase = abase + (uint32_t)(MTILE * A_STR) * 4; // E[256][68] fp32

    const int ksplit = blockIdx.x;
    const int mtile  = blockIdx.y;
    const int m_base = mtile * MTILE;
    const int k_base = ksplit * KSPLIT;
    const int k_len  = (ksplit < NSPLIT - 1) ? KSPLIT : (V_DIM - (NSPLIT - 1) * KSPLIT);
    const int nstages = (k_len + KC - 1) / KC;   // 8 (last split: 7)

    const float* inpS = inp + (size_t)m_base * V_DIM + k_base;
    const float* embS = emb + (size_t)k_base * D_DIM;

    const int tid  = threadIdx.x;
    const int warp = tid >> 5;
    const int lane = tid & 31;
    const int g = lane >> 2;          // 0..7
    const int t = lane & 3;           // 0..3
    const int warp_m = warp & 3;      // 32-row slab
    const int warp_n = warp >> 2;     // 32-col slab (0..1)

    float acc[2][4][4];
    #pragma unroll
    for (int i = 0; i < 2; i++)
        #pragma unroll
        for (int j = 0; j < 4; j++)
            #pragma unroll
            for (int r = 0; r < 4; r++) acc[i][j][r] = 0.0f;

    // ==== FLOOD: issue the ENTIRE split tile as cp.async, 8 k-ordered groups ====
    // Per stage s: A 1024 chunks (4/thread) + E 512 chunks (2/thread).
    #pragma unroll
    for (int s = 0; s < (KSPLIT / KC); s++) {
        #pragma unroll
        for (int i = 0; i < 4; i++) {
            int idx = tid + i * NTHREADS;        // 0..1023
            int r = idx >> 3, q = idx & 7;       // row, 16B-quad within stage
            int k = s * KC + q * 4;
            bool p = (k < k_len);                // k_len mult of 16 -> chunk-granular
            cp_async16(abase + (uint32_t)(r * A_STR + k) * 4u,
                       inpS + (size_t)r * V_DIM + (p ? k : 0), p);
        }
        #pragma unroll
        for (int i = 0; i < 2; i++) {
            int idx = tid + i * NTHREADS;        // 0..511
            int kr = idx >> 4, q = idx & 15;     // k-row within stage, quad
            int k = s * KC + kr;
            bool p = (k < k_len);
            cp_async16(ebase + (uint32_t)(k * E_STR + q * 4) * 4u,
                       embS + (size_t)(p ? k : 0) * D_DIM + q * 4, p);
        }
        cp_commit();
    }

    // ==== DRAIN: progressive waits + compute ====
    for (int it = 0; it < nstages; it++) {
        cp_wait_n((KSPLIT / KC) - 1 - it);   // groups 0..it complete
        __syncthreads();                     // arrivals visible CTA-wide

        #pragma unroll
        for (int kk = 0; kk < KC; kk += 8) {
            const int kc = it * KC + kk;
            uint32_t a[2][4], b[4][2];
            #pragma unroll
            for (int mt = 0; mt < 2; mt++) {
                uint32_t r0 = (uint32_t)(warp_m * 32 + mt * 16 + g);
                uint32_t b0 = abase + (r0 * A_STR + (uint32_t)(kc + t)) * 4u;
                uint32_t b1 = b0 + 8u * A_STR * 4u;
                a[mt][0] = lds32(b0);
                a[mt][1] = lds32(b1);
                a[mt][2] = lds32(b0 + 16u);      // k + 4
                a[mt][3] = lds32(b1 + 16u);
            }
            #pragma unroll
            for (int nt = 0; nt < 4; nt++) {
                uint32_t col = (uint32_t)(warp_n * 32 + nt * 8 + g);
                uint32_t cb = ebase + ((uint32_t)(kc + t) * E_STR + col) * 4u;
                b[nt][0] = f2tf32(lds32f(cb));
                b[nt][1] = f2tf32(lds32f(cb + 4u * E_STR * 4u));   // k + 4
            }
            #pragma unroll
            for (int mt = 0; mt < 2; mt++)
                #pragma unroll
                for (int nt = 0; nt < 4; nt++)
                    asm volatile(
                        "mma.sync.aligned.m16n8k8.row.col.f32.tf32.tf32.f32 "
                        "{%0,%1,%2,%3}, {%4,%5,%6,%7}, {%8,%9}, {%0,%1,%2,%3};"
                        : "+f"(acc[mt][nt][0]), "+f"(acc[mt][nt][1]),
                          "+f"(acc[mt][nt][2]), "+f"(acc[mt][nt][3])
                        : "r"(a[mt][0]), "r"(a[mt][1]), "r"(a[mt][2]), "r"(a[mt][3]),
                          "r"(b[nt][0]), "r"(b[nt][1]));
        }
    }

    // ==== write 128x64 fp32 partial tile ====
    float* pp = &g_partials[ksplit][m_base][0];
    #pragma unroll
    for (int mt = 0; mt < 2; mt++) {
        int m0 = warp_m * 32 + mt * 16;
        #pragma unroll
        for (int nt = 0; nt < 4; nt++) {
            int n0 = warp_n * 32 + nt * 8 + 2 * t;
            pp[(m0 + g)     * D_DIM + n0]     = acc[mt][nt][0];
            pp[(m0 + g)     * D_DIM + n0 + 1] = acc[mt][nt][1];
            pp[(m0 + g + 8) * D_DIM + n0]     = acc[mt][nt][2];
            pp[(m0 + g + 8) * D_DIM + n0 + 1] = acc[mt][nt][3];
        }
    }

    // ==== fused deterministic split-K reduction (128 CTAs co-resident) ====
    __syncthreads();
    if (tid == 0) {
        __threadfence();                       // release partial stores
        atomicAdd(&g_arrive[mtile], 1u);
        unsigned v;
        do {
            asm volatile("ld.acquire.gpu.u32 %0, [%1];" : "=r"(v) : "l"(&g_arrive[mtile]));
            if (v >= NSPLIT) break;
            __nanosleep(64);
        } while (true);
    }
    __syncthreads();   // propagate tid0's acquire CTA-wide

    {   // this CTA reduces rows [m_base + ksplit*16, +16): 256 float4, 1/thread
        int r = tid >> 4, q = tid & 15;
        int off = (m_base + ksplit * 16 + r) * (D_DIM / 4) + q;
        const float4* p = reinterpret_cast<const float4*>(&g_partials[0][0][0]);
        float4 s = p[off];
        #pragma unroll
        for (int sp = 1; sp < NSPLIT; sp++) {   // fixed order -> deterministic
            float4 v = p[(size_t)sp * (B_DIM * D_DIM / 4) + off];
            s.x += v.x; s.y += v.y; s.z += v.z; s.w += v.w;
        }
        reinterpret_cast<float4*>(out)[off] = s;
    }

    __syncthreads();
    if (tid == 0) {   // reset counters for graph replay
        unsigned d = atomicAdd(&g_done[mtile], 1u);
        if (d == NSPLIT - 1) {
            atomicExch(&g_arrive[mtile], 0u);
            atomicExch(&g_done[mtile], 0u);
        }
    }
}

extern "C" void kernel_launch(void* const* d_in, const int* in_sizes, int n_in,
                              void* d_out, int out_size)
{
    const float* inputs     = (const float*)d_in[0];   // (B, V) fp32
    const float* embeddings = (const float*)d_in[1];   // (V, D) fp32
    float* out = (float*)d_out;                        // (B, D) fp32

    cudaFuncSetAttribute(embedweighted_flood,
                         cudaFuncAttributeMaxDynamicSharedMemorySize, DYN_BYTES);

    dim3 grid(NSPLIT, NMTILE);   // 128 CTAs, occ 1 -> all co-resident
    embedweighted_flood<<<grid, NTHREADS, DYN_BYTES>>>(inputs, embeddings, out);
}

// round 13
// speedup vs baseline: 1.2678x; 1.2678x over previous
#include <cuda_runtime.h>
#include <cstdint>

// EmbedWeighted == out(B,D) = inputs(B,V) @ embeddings(V,D)
// R11 barrier-free streaming fp16 mma.sync + L2::256B prefetch-hinted A stream.
#define B_DIM 2048
#define V_DIM 2000
#define D_DIM 64
#define NSPLIT 8
#define KSPLIT 256            // splits 0..6: 256 (16 k16 steps); split 7: 208 (13)
#define NTHREADS 256
#define MTILE 128
#define NMTILE (B_DIM / MTILE)            // 16
#define ET_STR 132            // words per Et row (264 halves): 4 mod 32 -> banks ok

__device__ float g_partials[NSPLIT][B_DIM][D_DIM];   // 4 MB static scratch
__device__ unsigned g_arrive[NMTILE];                // zero-init, self-resetting
__device__ unsigned g_done[NMTILE];

static __device__ __forceinline__ uint32_t smem_u32(const void* p) {
    return (uint32_t)__cvta_generic_to_shared(p);
}
static __device__ __forceinline__ uint32_t lds32(uint32_t a) {
    uint32_t v; asm("ld.shared.b32 %0, [%1];" : "=r"(v) : "r"(a)); return v;
}
static __device__ __forceinline__ uint32_t pack_h2(float lo, float hi) {
    uint32_t r;   // d.hi = cvt(%1), d.lo = cvt(%2)
    asm("cvt.rn.f16x2.f32 %0, %1, %2;" : "=r"(r) : "f"(hi), "f"(lo));
    return r;
}
// A stream load: 8B used, 256B prefetched into L2 (covers the next 3 k-steps)
static __device__ __forceinline__ float2 ldgA2(const float* p) {
    float2 v;
    asm("ld.global.nc.L2::256B.v2.f32 {%0,%1}, [%2];"
        : "=f"(v.x), "=f"(v.y) : "l"(p));
    return v;
}
static __device__ __forceinline__ float ldgE(const float* p) {
    float v;
    asm("ld.global.nc.L2::256B.f32 %0, [%1];" : "=f"(v) : "l"(p));
    return v;
}

// 256 threads, 8 warps; warp tile 16m x 64n. CTA tile 128x64.
// grid (8, 16) = 128 CTAs (one wave) -> all co-resident.
__global__ __launch_bounds__(NTHREADS, 2)
void embedweighted_pf(const float* __restrict__ inp,
                      const float* __restrict__ emb,
                      float* __restrict__ out)
{
    __shared__ __align__(16) uint32_t Et[D_DIM * ET_STR];   // fp16 Et[n][k], 33.8 KB

    const int ksplit = blockIdx.x;
    const int mtile  = blockIdx.y;
    const int m_base = mtile * MTILE;
    const int k_base = ksplit * KSPLIT;
    const int k_len  = (ksplit < NSPLIT - 1) ? KSPLIT : (V_DIM - (NSPLIT - 1) * KSPLIT);
    const int nk     = k_len >> 4;    // 16, last split 13 (exact)

    const int tid  = threadIdx.x;
    const int warp = tid >> 5;        // 0..7 -> rows m_base + warp*16 ..
    const int lane = tid & 31;
    const int g = lane >> 2;          // 0..7
    const int t = lane & 3;           // 0..3

    // ---- stage E once: Et[n][k] fp16, k zero-filled beyond V_DIM ----
    {
        const int en = tid & 63;      // n
        const int kb = tid >> 6;      // k-block 0..3 (64 k each)
        #pragma unroll
        for (int i = 0; i < 32; i++) {
            int k0 = k_base + kb * 64 + 2 * i;
            float f0 = (k0     < V_DIM) ? ldgE(emb + (size_t)k0 * D_DIM + en)       : 0.f;
            float f1 = (k0 + 1 < V_DIM) ? ldgE(emb + (size_t)(k0 + 1) * D_DIM + en) : 0.f;
            Et[en * ET_STR + kb * 32 + i] = pack_h2(f0, f1);
        }
    }

    // first two A k-steps prefetched into registers (independent of smem)
    const float* a0p = inp + (size_t)(m_base + warp * 16 + g) * V_DIM + k_base + 2 * t;
    const float* a8p = a0p + 8 * (size_t)V_DIM;
    float2 c0 = ldgA2(a0p),      c1 = ldgA2(a8p);
    float2 c2 = ldgA2(a0p + 8),  c3 = ldgA2(a8p + 8);
    float2 d0 = ldgA2(a0p + 16), d1 = ldgA2(a8p + 16);
    float2 d2 = ldgA2(a0p + 24), d3 = ldgA2(a8p + 24);

    __syncthreads();   // the ONLY gemm barrier: Et visible

    float acc[8][4];
    #pragma unroll
    for (int j = 0; j < 8; j++)
        #pragma unroll
        for (int r = 0; r < 4; r++) acc[j][r] = 0.0f;

    // ---- barrier-free mainloop: per-warp independent stream, distance-2 prefetch ----
    const uint32_t eb = smem_u32(Et) + (uint32_t)(g * ET_STR + t) * 4u;
    for (int ks = 0; ks < nk; ks++) {
        float2 n0 = c0, n1 = c1, n2 = c2, n3 = c3;   // default init (tail)
        if (ks + 2 < nk) {
            int off = (ks + 2) * 16;
            n0 = ldgA2(a0p + off);      n1 = ldgA2(a8p + off);
            n2 = ldgA2(a0p + off + 8);  n3 = ldgA2(a8p + off + 8);
        }
        const uint32_t a0 = pack_h2(c0.x, c0.y);
        const uint32_t a1 = pack_h2(c1.x, c1.y);
        const uint32_t a2 = pack_h2(c2.x, c2.y);
        const uint32_t a3 = pack_h2(c3.x, c3.y);

        const uint32_t ecur = eb + (uint32_t)(ks * 8) * 4u;
        #pragma unroll
        for (int nt = 0; nt < 8; nt++) {
            uint32_t b0 = lds32(ecur + (uint32_t)(nt * 8 * ET_STR) * 4u);
            uint32_t b1 = lds32(ecur + (uint32_t)(nt * 8 * ET_STR + 4) * 4u);
            asm volatile(
                "mma.sync.aligned.m16n8k16.row.col.f32.f16.f16.f32 "
                "{%0,%1,%2,%3}, {%4,%5,%6,%7}, {%8,%9}, {%0,%1,%2,%3};"
                : "+f"(acc[nt][0]), "+f"(acc[nt][1]),
                  "+f"(acc[nt][2]), "+f"(acc[nt][3])
                : "r"(a0), "r"(a1), "r"(a2), "r"(a3), "r"(b0), "r"(b1));
        }
        c0 = d0; c1 = d1; c2 = d2; c3 = d3;
        d0 = n0; d1 = n1; d2 = n2; d3 = n3;
    }

    // ---- write 16x64 fp32 partial strip per warp ----
    {
        float* pp = &g_partials[ksplit][m_base + warp * 16][0];
        #pragma unroll
        for (int nt = 0; nt < 8; nt++) {
            int n0c = nt * 8 + 2 * t;
            pp[g * D_DIM + n0c]           = acc[nt][0];
            pp[g * D_DIM + n0c + 1]       = acc[nt][1];
            pp[(g + 8) * D_DIM + n0c]     = acc[nt][2];
            pp[(g + 8) * D_DIM + n0c + 1] = acc[nt][3];
        }
    }

    // ---- fused deterministic split-K reduction (all 128 CTAs co-resident) ----
    __syncthreads();
    if (tid == 0) {
        __threadfence();                       // release partial stores
        atomicAdd(&g_arrive[mtile], 1u);
        unsigned v;
        do {
            asm volatile("ld.acquire.gpu.u32 %0, [%1];" : "=r"(v) : "l"(&g_arrive[mtile]));
            if (v >= NSPLIT) break;
            __nanosleep(64);
        } while (true);
    }
    __syncthreads();   // propagate tid0's acquire CTA-wide

    {   // this CTA reduces rows [m_base + ksplit*16, +16): 256 float4, 1/thread
        int r = tid >> 4, q = tid & 15;
        int off = (m_base + ksplit * 16 + r) * (D_DIM / 4) + q;
        const float4* p = reinterpret_cast<const float4*>(&g_partials[0][0][0]);
        float4 s = p[off];
        #pragma unroll
        for (int sp = 1; sp < NSPLIT; sp++) {   // fixed order -> deterministic
            float4 v = p[(size_t)sp * (B_DIM * D_DIM / 4) + off];
            s.x += v.x; s.y += v.y; s.z += v.z; s.w += v.w;
        }
        reinterpret_cast<float4*>(out)[off] = s;
    }

    __syncthreads();
    if (tid == 0) {   // reset counters for graph replay
        unsigned d = atomicAdd(&g_done[mtile], 1u);
        if (d == NSPLIT - 1) {
            atomicExch(&g_arrive[mtile], 0u);
            atomicExch(&g_done[mtile], 0u);
        }
    }
}

extern "C" void kernel_launch(void* const* d_in, const int* in_sizes, int n_in,
                              void* d_out, int out_size)
{
    const float* inputs     = (const float*)d_in[0];   // (B, V) fp32
    const float* embeddings = (const float*)d_in[1];   // (V, D) fp32
    float* out = (float*)d_out;                        // (B, D) fp32

    dim3 grid(NSPLIT, NMTILE);   // 128 CTAs == one wave, all co-resident
    embedweighted_pf<<<grid, NTHREADS>>>(inputs, embeddings, out);
}